// round 6
// baseline (speedup 1.0000x reference)
#include <cuda_runtime.h>
#include <cstdint>

// SuperchargingBKT — warp-per-row 2x2 projective matrix scan, round 5.
//
// R5: cp.async-staged gathers. R3 (occupancy+50%) and R4 (L1 traffic -33%)
// both moved dur <5% with issue pinned at ~20% -> kernel is exposed-gather-
// latency bound, MLP capped by registers. Fix: issue all 16 steps' ability
// (cp.async.cg 16B, L1-bypass) and omega/sigma (cp.async.ca 8B) gathers into
// smem up front, two commit groups (compute steps 0-7 overlaps landing of
// 8-15). Coefficient cache reuses the raw-gather smem in place.
//
// Inputs (metadata order):
//  0 pL0_logit [K] f32   4 pS_logit [K] f32    8 observations [B,T] i32
//  1 pT_logit  [K] f32   5 omega    [P] f32    9 kc_ids       [B,T] i32
//  2 pF_logit  [K] f32   6 sigma    [P] f32   10 problem_ids  [B,T] i32
//  3 pG_logit  [K] f32   7 ability  [S,4] f32 11 student_ids  [B,T] i32
// Output: p_correct [B,T] f32

constexpr int T_LEN = 512;
constexpr int SEG   = 16;                 // steps per lane (32 lanes * 16 = 512)
constexpr int THREADS = 256;
constexpr int K_CAP = 1024;               // K = 1000
constexpr int P_CAP = 50048;              // P = 50000

constexpr int SMEM_KC  = K_CAP * 16;                    // 16KB kc table
constexpr int SMEM_TH  = SEG * THREADS * 16;            // 64KB ability / coeffs
constexpr int SMEM_PS  = SEG * THREADS * 8;             // 32KB omega,sigma
constexpr int SMEM_TOTAL = SMEM_KC + SMEM_TH + SMEM_PS; // 112KB

__device__ float4 g_kcpack[K_CAP];        // (pT,pF,pG,pS) logits per KC
__device__ float2 g_pspack[P_CAP];        // (omega,sigma) per problem

__device__ __forceinline__ float sigmoidf(float x) {
    return __fdividef(1.0f, 1.0f + __expf(-x));
}

__device__ __forceinline__ void cp_async16_cg(uint32_t dst, const void* src) {
    asm volatile("cp.async.cg.shared.global [%0], [%1], 16;\n"
                 :: "r"(dst), "l"(src));
}
__device__ __forceinline__ void cp_async8_ca(uint32_t dst, const void* src) {
    asm volatile("cp.async.ca.shared.global [%0], [%1], 8;\n"
                 :: "r"(dst), "l"(src));
}
__device__ __forceinline__ void cp_commit() {
    asm volatile("cp.async.commit_group;\n" ::: "memory");
}
template <int N>
__device__ __forceinline__ void cp_wait() {
    asm volatile("cp.async.wait_group %0;\n" :: "n"(N) : "memory");
}

__global__ void pack_tables(
    const float* __restrict__ pT_logit, const float* __restrict__ pF_logit,
    const float* __restrict__ pG_logit, const float* __restrict__ pS_logit,
    const float* __restrict__ omega,    const float* __restrict__ sigma,
    int K, int P)
{
    int i = blockIdx.x * blockDim.x + threadIdx.x;
    if (i < K)
        g_kcpack[i] = make_float4(pT_logit[i], pF_logit[i], pG_logit[i], pS_logit[i]);
    if (i < P)
        g_pspack[i] = make_float2(omega[i], sigma[i]);
}

__global__ void __launch_bounds__(THREADS, 2)
bkt_warp_scan(
    const float* __restrict__ pL0_logit,
    const float4* __restrict__ ability,
    const int*  __restrict__ obs,
    const int*  __restrict__ kc,
    const int*  __restrict__ pid,
    const int*  __restrict__ sid,
    float* __restrict__ out,
    int B, int K)
{
    extern __shared__ char smem[];
    float4* kcTab = reinterpret_cast<float4*>(smem);               // [K_CAP]
    float4* rawTh = reinterpret_cast<float4*>(smem + SMEM_KC);     // [SEG][THREADS] th -> c1..c4
    float2* rawPs = reinterpret_cast<float2*>(smem + SMEM_KC + SMEM_TH); // [SEG][THREADS]

    const int tid  = threadIdx.x;
    const int lane = tid & 31;
    const int warp = (blockIdx.x * blockDim.x + tid) >> 5;

    // stage KC table (coalesced); all threads reach this barrier
    for (int i = tid; i < K; i += THREADS) kcTab[i] = g_kcpack[i];
    __syncthreads();

    if (warp >= B) return;

    const int base = warp * T_LEN;
    const int s0   = base + lane * SEG;

    // ---- load all index vectors for this lane's 16 steps ----
    int kk[SEG]; int pp[SEG]; int ss[SEG];
    unsigned obits = 0;
#pragma unroll
    for (int q = 0; q < SEG / 4; ++q) {
        const int o4i = s0 + 4 * q;
        int4 kv = *reinterpret_cast<const int4*>(kc  + o4i);
        int4 pv = *reinterpret_cast<const int4*>(pid + o4i);
        int4 sv = *reinterpret_cast<const int4*>(sid + o4i);
        int4 ov = *reinterpret_cast<const int4*>(obs + o4i);
        kk[4*q+0] = kv.x; kk[4*q+1] = kv.y; kk[4*q+2] = kv.z; kk[4*q+3] = kv.w;
        pp[4*q+0] = pv.x; pp[4*q+1] = pv.y; pp[4*q+2] = pv.z; pp[4*q+3] = pv.w;
        ss[4*q+0] = sv.x; ss[4*q+1] = sv.y; ss[4*q+2] = sv.z; ss[4*q+3] = sv.w;
        obits |= (ov.x != 0 ? 1u : 0u) << (4*q+0);
        obits |= (ov.y != 0 ? 1u : 0u) << (4*q+1);
        obits |= (ov.z != 0 ? 1u : 0u) << (4*q+2);
        obits |= (ov.w != 0 ? 1u : 0u) << (4*q+3);
    }

    // ---- issue ALL gathers via cp.async: group A = steps 0..7, B = 8..15 ----
    const uint32_t thBase = (uint32_t)__cvta_generic_to_shared(rawTh);
    const uint32_t psBase = (uint32_t)__cvta_generic_to_shared(rawPs);
#pragma unroll
    for (int i = 0; i < SEG / 2; ++i) {
        cp_async16_cg(thBase + (i * THREADS + tid) * 16, ability  + ss[i]);
        cp_async8_ca (psBase + (i * THREADS + tid) * 8,  g_pspack + pp[i]);
    }
    cp_commit();
#pragma unroll
    for (int i = SEG / 2; i < SEG; ++i) {
        cp_async16_cg(thBase + (i * THREADS + tid) * 16, ability  + ss[i]);
        cp_async8_ca (psBase + (i * THREADS + tid) * 8,  g_pspack + pp[i]);
    }
    cp_commit();

    // initial state (overlaps with in-flight gathers)
    float pL0 = sigmoidf(__ldg(pL0_logit + __ldg(kc + base)));

    // A maps segment-start state (hu,hm) -> state after processed steps.
    float a00 = 1.f, a01 = 0.f, a10 = 0.f, a11 = 1.f;

    // ---- pass 1: coefficients + segment matrix product (two halves) -------
#pragma unroll
    for (int half = 0; half < 2; ++half) {
        if (half == 0) cp_wait<1>(); else cp_wait<0>();
#pragma unroll
        for (int j = 0; j < SEG / 2; ++j) {
            const int i = half * (SEG / 2) + j;
            float4 th  = rawTh[i * THREADS + tid];
            float2 psp = rawPs[i * THREADS + tid];
            float4 kcp = kcTab[kk[i]];            // LDS.128 gather
            float pT = sigmoidf(kcp.x + th.x);
            float pF = sigmoidf(kcp.y - th.y);
            float pG = sigmoidf(kcp.z + psp.x + th.z);
            float pS = sigmoidf(kcp.w + psp.y - th.w);
            bool o = (obits >> i) & 1u;
            float pom = o ? (1.0f - pS) : pS;      // P(y | mastered)
            float pou = o ? pG : (1.0f - pG);      // P(y | unmastered)
            float c1 = (1.0f - pF) * pom;
            float c2 = pT * pou;
            float c3 = pF * pom;
            float c4 = (1.0f - pT) * pou;
            rawTh[i * THREADS + tid] = make_float4(c1, c2, c3, c4); // in-place

            // A = M * A,  M = [[c4,c3],[c2,c1]]
            float n00 = fmaf(c4, a00, c3 * a10);
            float n01 = fmaf(c4, a01, c3 * a11);
            float n10 = fmaf(c2, a00, c1 * a10);
            float n11 = fmaf(c2, a01, c1 * a11);
            a00 = n00; a01 = n01; a10 = n10; a11 = n11;

            if ((i & 7) == 7) {   // normalize every 8 steps
                float r = __fdividef(1.0f, a00 + a01 + a10 + a11);
                a00 *= r; a01 *= r; a10 *= r; a11 *= r;
            }
        }
    }

    // ------------- inclusive warp scan of segment matrices -----------------
#pragma unroll
    for (int d = 1; d < 32; d <<= 1) {
        float b00 = __shfl_up_sync(0xFFFFFFFFu, a00, d);
        float b01 = __shfl_up_sync(0xFFFFFFFFu, a01, d);
        float b10 = __shfl_up_sync(0xFFFFFFFFu, a10, d);
        float b11 = __shfl_up_sync(0xFFFFFFFFu, a11, d);
        if (lane >= d) {
            float n00 = fmaf(a00, b00, a01 * b10);   // mine(later) * other(earlier)
            float n01 = fmaf(a00, b01, a01 * b11);
            float n10 = fmaf(a10, b00, a11 * b10);
            float n11 = fmaf(a10, b01, a11 * b11);
            float r = __fdividef(1.0f, n00 + n01 + n10 + n11);
            a00 = n00 * r; a01 = n01 * r; a10 = n10 * r; a11 = n11 * r;
        }
    }

    // exclusive prefix
    float e00 = __shfl_up_sync(0xFFFFFFFFu, a00, 1);
    float e01 = __shfl_up_sync(0xFFFFFFFFu, a01, 1);
    float e10 = __shfl_up_sync(0xFFFFFFFFu, a10, 1);
    float e11 = __shfl_up_sync(0xFFFFFFFFu, a11, 1);
    if (lane == 0) { e00 = 1.f; e01 = 0.f; e10 = 0.f; e11 = 1.f; }

    float hu0 = 1.0f - pL0;
    float hm0 = pL0;
    float hu = fmaf(e00, hu0, e01 * hm0);
    float hm = fmaf(e10, hu0, e11 * hm0);
    float rs = __fdividef(1.0f, hu + hm);
    hu *= rs; hm *= rs;

    // ---------------- pass 2: replay segment, emit p_correct ---------------
    float* op = out + s0;
#pragma unroll
    for (int q = 0; q < SEG / 4; ++q) {
        float4 res;
        float* r4 = reinterpret_cast<float*>(&res);
#pragma unroll
        for (int j = 0; j < 4; ++j) {
            const int i = 4 * q + j;
            float4 cc = rawTh[i * THREADS + tid];   // (c1,c2,c3,c4)
            float nm = fmaf(cc.x, hm, cc.y * hu);
            float nu = fmaf(cc.z, hm, cc.w * hu);
            float r  = __fdividef(1.0f, nm + nu);
            hm = nm * r;
            hu = nu * r;
            bool o = (obits >> i) & 1u;
            float pom = cc.x + cc.z;               // = 1-pS if o else pS
            float pou = cc.y + cc.w;               // = pG   if o else 1-pG
            float c5 = o ? pom : (1.0f - pom);     // 1-pS
            float c6 = o ? pou : (1.0f - pou);     // pG
            r4[j] = fmaf(c5, hm, c6 * hu);
        }
        *reinterpret_cast<float4*>(op + 4 * q) = res;
    }
}

extern "C" void kernel_launch(void* const* d_in, const int* in_sizes, int n_in,
                              void* d_out, int out_size) {
    const float* pL0 = (const float*)d_in[0];
    const float* pT  = (const float*)d_in[1];
    const float* pF  = (const float*)d_in[2];
    const float* pG  = (const float*)d_in[3];
    const float* pS  = (const float*)d_in[4];
    const float* om  = (const float*)d_in[5];
    const float* sg  = (const float*)d_in[6];
    const float4* ab = (const float4*)d_in[7];
    const int* obs = (const int*)d_in[8];
    const int* kc  = (const int*)d_in[9];
    const int* pid = (const int*)d_in[10];
    const int* sid = (const int*)d_in[11];
    float* out = (float*)d_out;

    int K = in_sizes[0];                  // 1000
    int P = in_sizes[5];                  // 50000
    int B = in_sizes[8] / T_LEN;          // 8192 rows
    if (K > K_CAP) K = K_CAP;
    if (P > P_CAP) P = P_CAP;

    cudaFuncSetAttribute(bkt_warp_scan,
                         cudaFuncAttributeMaxDynamicSharedMemorySize, SMEM_TOTAL);

    int n = (K > P) ? K : P;
    pack_tables<<<(n + 255) / 256, 256>>>(pT, pF, pG, pS, om, sg, K, P);

    int warps_per_block = THREADS / 32;
    int grid = (B + warps_per_block - 1) / warps_per_block;
    bkt_warp_scan<<<grid, THREADS, SMEM_TOTAL>>>(pL0, ab, obs, kc, pid, sid,
                                                 out, B, K);
}

// round 7
// speedup vs baseline: 1.0625x; 1.0625x over previous
#include <cuda_runtime.h>
#include <cstdint>

// SuperchargingBKT — warp-per-row 2x2 projective matrix scan, round 6.
//
// R6 = cp.async gather staging (validated by R5's L1% drop) configured right:
//  * THREADS=128 -> smem 64KB/CTA -> 3 CTAs/SM (R5 had 112KB -> 2).
//  * indices consumed at cp.async issue; only kk[16]+obits persist (R5 kept
//    kk/pp/ss arrays -> 118 regs).
//  * 4 commit groups of 4 steps: first wait covers 1/4 of traffic, later
//    waits arrive pre-satisfied (R5's 2 groups exposed full latency).
// Gathers: ability 16B cp.async.cg (L1-bypass), omega/sigma 8B cp.async.ca,
// KC table LDS.128 from smem. Ability stage is overwritten in place with
// coefficients (c1..c4) for pass 2.
//
// Inputs (metadata order):
//  0 pL0_logit [K] f32   4 pS_logit [K] f32    8 observations [B,T] i32
//  1 pT_logit  [K] f32   5 omega    [P] f32    9 kc_ids       [B,T] i32
//  2 pF_logit  [K] f32   6 sigma    [P] f32   10 problem_ids  [B,T] i32
//  3 pG_logit  [K] f32   7 ability  [S,4] f32 11 student_ids  [B,T] i32
// Output: p_correct [B,T] f32

constexpr int T_LEN = 512;
constexpr int SEG   = 16;                 // steps per lane (32 lanes * 16 = 512)
constexpr int THREADS = 128;
constexpr int K_CAP = 1024;               // K = 1000
constexpr int P_CAP = 50048;              // P = 50000

constexpr int SMEM_KC  = K_CAP * 16;                    // 16KB kc table
constexpr int SMEM_TH  = SEG * THREADS * 16;            // 32KB ability -> coeffs
constexpr int SMEM_PS  = SEG * THREADS * 8;             // 16KB omega,sigma
constexpr int SMEM_TOTAL = SMEM_KC + SMEM_TH + SMEM_PS; // 64KB -> 3 CTAs/SM

__device__ float4 g_kcpack[K_CAP];        // (pT,pF,pG,pS) logits per KC
__device__ float2 g_pspack[P_CAP];        // (omega,sigma) per problem

__device__ __forceinline__ float sigmoidf(float x) {
    return __fdividef(1.0f, 1.0f + __expf(-x));
}

__device__ __forceinline__ void cp_async16_cg(uint32_t dst, const void* src) {
    asm volatile("cp.async.cg.shared.global [%0], [%1], 16;\n"
                 :: "r"(dst), "l"(src));
}
__device__ __forceinline__ void cp_async8_ca(uint32_t dst, const void* src) {
    asm volatile("cp.async.ca.shared.global [%0], [%1], 8;\n"
                 :: "r"(dst), "l"(src));
}
__device__ __forceinline__ void cp_commit() {
    asm volatile("cp.async.commit_group;\n" ::: "memory");
}
template <int N>
__device__ __forceinline__ void cp_wait() {
    asm volatile("cp.async.wait_group %0;\n" :: "n"(N) : "memory");
}

__global__ void pack_tables(
    const float* __restrict__ pT_logit, const float* __restrict__ pF_logit,
    const float* __restrict__ pG_logit, const float* __restrict__ pS_logit,
    const float* __restrict__ omega,    const float* __restrict__ sigma,
    int K, int P)
{
    int i = blockIdx.x * blockDim.x + threadIdx.x;
    if (i < K)
        g_kcpack[i] = make_float4(pT_logit[i], pF_logit[i], pG_logit[i], pS_logit[i]);
    if (i < P)
        g_pspack[i] = make_float2(omega[i], sigma[i]);
}

__global__ void __launch_bounds__(THREADS)
bkt_warp_scan(
    const float* __restrict__ pL0_logit,
    const float4* __restrict__ ability,
    const int*  __restrict__ obs,
    const int*  __restrict__ kc,
    const int*  __restrict__ pid,
    const int*  __restrict__ sid,
    float* __restrict__ out,
    int B, int K)
{
    extern __shared__ char smem[];
    float4* kcTab = reinterpret_cast<float4*>(smem);               // [K_CAP]
    float4* rawTh = reinterpret_cast<float4*>(smem + SMEM_KC);     // [SEG][THREADS] th -> c1..c4
    float2* rawPs = reinterpret_cast<float2*>(smem + SMEM_KC + SMEM_TH); // [SEG][THREADS]

    const int tid  = threadIdx.x;
    const int lane = tid & 31;
    const int warp = (blockIdx.x * blockDim.x + tid) >> 5;

    // stage KC table (coalesced); all threads reach this barrier
    for (int i = tid; i < K; i += THREADS) kcTab[i] = g_kcpack[i];
    __syncthreads();

    if (warp >= B) return;

    const int base = warp * T_LEN;
    const int s0   = base + lane * SEG;

    const uint32_t thBase = (uint32_t)__cvta_generic_to_shared(rawTh) + tid * 16u;
    const uint32_t psBase = (uint32_t)__cvta_generic_to_shared(rawPs) + tid * 8u;

    int kk[SEG];
    unsigned obits = 0;

    // ---- issue all gathers: 4 commit groups of 4 steps each ---------------
#pragma unroll
    for (int q = 0; q < SEG / 4; ++q) {
        const int o4i = s0 + 4 * q;
        int4 kv = *reinterpret_cast<const int4*>(kc  + o4i);
        int4 pv = *reinterpret_cast<const int4*>(pid + o4i);
        int4 sv = *reinterpret_cast<const int4*>(sid + o4i);
        int4 ov = *reinterpret_cast<const int4*>(obs + o4i);
        kk[4*q+0] = kv.x; kk[4*q+1] = kv.y; kk[4*q+2] = kv.z; kk[4*q+3] = kv.w;
        obits |= (ov.x != 0 ? 1u : 0u) << (4*q+0);
        obits |= (ov.y != 0 ? 1u : 0u) << (4*q+1);
        obits |= (ov.z != 0 ? 1u : 0u) << (4*q+2);
        obits |= (ov.w != 0 ? 1u : 0u) << (4*q+3);

        int ssr[4] = {sv.x, sv.y, sv.z, sv.w};
        int ppr[4] = {pv.x, pv.y, pv.z, pv.w};
#pragma unroll
        for (int j = 0; j < 4; ++j) {
            const int i = 4 * q + j;
            cp_async16_cg(thBase + i * (THREADS * 16), ability  + ssr[j]);
            cp_async8_ca (psBase + i * (THREADS * 8),  g_pspack + ppr[j]);
        }
        cp_commit();
    }

    // initial state (overlaps with in-flight gathers)
    float pL0 = sigmoidf(__ldg(pL0_logit + __ldg(kc + base)));

    // A maps segment-start state (hu,hm) -> state after processed steps.
    float a00 = 1.f, a01 = 0.f, a10 = 0.f, a11 = 1.f;

    // ---- pass 1: coefficients + segment matrix product, 4-step waves ------
#pragma unroll
    for (int q = 0; q < SEG / 4; ++q) {
        switch (q) {                    // wait for group q only
            case 0: cp_wait<3>(); break;
            case 1: cp_wait<2>(); break;
            case 2: cp_wait<1>(); break;
            default: cp_wait<0>(); break;
        }
#pragma unroll
        for (int j = 0; j < 4; ++j) {
            const int i = 4 * q + j;
            float4 th  = rawTh[i * THREADS + tid];
            float2 psp = rawPs[i * THREADS + tid];
            float4 kcp = kcTab[kk[i]];            // LDS.128 gather
            float pT = sigmoidf(kcp.x + th.x);
            float pF = sigmoidf(kcp.y - th.y);
            float pG = sigmoidf(kcp.z + psp.x + th.z);
            float pS = sigmoidf(kcp.w + psp.y - th.w);
            bool o = (obits >> i) & 1u;
            float pom = o ? (1.0f - pS) : pS;      // P(y | mastered)
            float pou = o ? pG : (1.0f - pG);      // P(y | unmastered)
            float c1 = (1.0f - pF) * pom;
            float c2 = pT * pou;
            float c3 = pF * pom;
            float c4 = (1.0f - pT) * pou;
            rawTh[i * THREADS + tid] = make_float4(c1, c2, c3, c4); // in-place

            // A = M * A,  M = [[c4,c3],[c2,c1]]
            float n00 = fmaf(c4, a00, c3 * a10);
            float n01 = fmaf(c4, a01, c3 * a11);
            float n10 = fmaf(c2, a00, c1 * a10);
            float n11 = fmaf(c2, a01, c1 * a11);
            a00 = n00; a01 = n01; a10 = n10; a11 = n11;
        }
        if (q & 1) {                    // normalize every 8 steps
            float r = __fdividef(1.0f, a00 + a01 + a10 + a11);
            a00 *= r; a01 *= r; a10 *= r; a11 *= r;
        }
    }

    // ------------- inclusive warp scan of segment matrices -----------------
#pragma unroll
    for (int d = 1; d < 32; d <<= 1) {
        float b00 = __shfl_up_sync(0xFFFFFFFFu, a00, d);
        float b01 = __shfl_up_sync(0xFFFFFFFFu, a01, d);
        float b10 = __shfl_up_sync(0xFFFFFFFFu, a10, d);
        float b11 = __shfl_up_sync(0xFFFFFFFFu, a11, d);
        if (lane >= d) {
            float n00 = fmaf(a00, b00, a01 * b10);   // mine(later) * other(earlier)
            float n01 = fmaf(a00, b01, a01 * b11);
            float n10 = fmaf(a10, b00, a11 * b10);
            float n11 = fmaf(a10, b01, a11 * b11);
            float r = __fdividef(1.0f, n00 + n01 + n10 + n11);
            a00 = n00 * r; a01 = n01 * r; a10 = n10 * r; a11 = n11 * r;
        }
    }

    // exclusive prefix
    float e00 = __shfl_up_sync(0xFFFFFFFFu, a00, 1);
    float e01 = __shfl_up_sync(0xFFFFFFFFu, a01, 1);
    float e10 = __shfl_up_sync(0xFFFFFFFFu, a10, 1);
    float e11 = __shfl_up_sync(0xFFFFFFFFu, a11, 1);
    if (lane == 0) { e00 = 1.f; e01 = 0.f; e10 = 0.f; e11 = 1.f; }

    float hu0 = 1.0f - pL0;
    float hm0 = pL0;
    float hu = fmaf(e00, hu0, e01 * hm0);
    float hm = fmaf(e10, hu0, e11 * hm0);
    float rs = __fdividef(1.0f, hu + hm);
    hu *= rs; hm *= rs;

    // ---------------- pass 2: replay segment, emit p_correct ---------------
    float* op = out + s0;
#pragma unroll
    for (int q = 0; q < SEG / 4; ++q) {
        float4 res;
        float* r4 = reinterpret_cast<float*>(&res);
#pragma unroll
        for (int j = 0; j < 4; ++j) {
            const int i = 4 * q + j;
            float4 cc = rawTh[i * THREADS + tid];   // (c1,c2,c3,c4)
            float nm = fmaf(cc.x, hm, cc.y * hu);
            float nu = fmaf(cc.z, hm, cc.w * hu);
            float r  = __fdividef(1.0f, nm + nu);
            hm = nm * r;
            hu = nu * r;
            bool o = (obits >> i) & 1u;
            float pom = cc.x + cc.z;               // = 1-pS if o else pS
            float pou = cc.y + cc.w;               // = pG   if o else 1-pG
            float c5 = o ? pom : (1.0f - pom);     // 1-pS
            float c6 = o ? pou : (1.0f - pou);     // pG
            r4[j] = fmaf(c5, hm, c6 * hu);
        }
        *reinterpret_cast<float4*>(op + 4 * q) = res;
    }
}

extern "C" void kernel_launch(void* const* d_in, const int* in_sizes, int n_in,
                              void* d_out, int out_size) {
    const float* pL0 = (const float*)d_in[0];
    const float* pT  = (const float*)d_in[1];
    const float* pF  = (const float*)d_in[2];
    const float* pG  = (const float*)d_in[3];
    const float* pS  = (const float*)d_in[4];
    const float* om  = (const float*)d_in[5];
    const float* sg  = (const float*)d_in[6];
    const float4* ab = (const float4*)d_in[7];
    const int* obs = (const int*)d_in[8];
    const int* kc  = (const int*)d_in[9];
    const int* pid = (const int*)d_in[10];
    const int* sid = (const int*)d_in[11];
    float* out = (float*)d_out;

    int K = in_sizes[0];                  // 1000
    int P = in_sizes[5];                  // 50000
    int B = in_sizes[8] / T_LEN;          // 8192 rows
    if (K > K_CAP) K = K_CAP;
    if (P > P_CAP) P = P_CAP;

    cudaFuncSetAttribute(bkt_warp_scan,
                         cudaFuncAttributeMaxDynamicSharedMemorySize, SMEM_TOTAL);

    int n = (K > P) ? K : P;
    pack_tables<<<(n + 255) / 256, 256>>>(pT, pF, pG, pS, om, sg, K, P);

    int warps_per_block = THREADS / 32;
    int grid = (B + warps_per_block - 1) / warps_per_block;
    bkt_warp_scan<<<grid, THREADS, SMEM_TOTAL>>>(pL0, ab, obs, kc, pid, sid,
                                                 out, B, K);
}